// round 6
// baseline (speedup 1.0000x reference)
#include <cuda_runtime.h>
#include <math.h>

// Problem constants
#define SEQ   4096
#define HID   2048
#define RNK   1024
#define NHEAD 16
#define DHEAD 128

// Scratch (device globals: allocation-free per harness rules)
__device__ float g_T[3 * SEQ * RNK];     // low-rank intermediates  (48 MB)
__device__ float g_QKV[3 * SEQ * HID];   // Q, K, V                 (96 MB)
__device__ float g_AO[SEQ * HID];        // attention output        (32 MB)

// ---------------------------------------------------------------------------
// SGEMM (NT): C[M,N] = A[M,K] * B[N,K]^T (+ bias[N]).  All dims % 128 == 0,
// K % 16 == 0.  128x128 tile, BK=16, 256 threads, 8x8 per-thread fragment.
// ---------------------------------------------------------------------------
__global__ __launch_bounds__(256)
void sgemm_nt(const float* __restrict__ A, const float* __restrict__ B,
              float* __restrict__ C, const float* __restrict__ bias,
              int M, int N, int K)
{
    __shared__ float As[16][128];
    __shared__ float Bs[16][128];

    const int tid = threadIdx.x;
    const int m0 = blockIdx.y * 128;
    const int n0 = blockIdx.x * 128;
    const int tx = tid & 15;          // 16 col-groups of 8
    const int ty = tid >> 4;          // 16 row-groups of 8
    const int lrow = tid >> 2;        // 0..63 loader row
    const int lcol = (tid & 3) << 2;  // 0,4,8,12 loader col

    float acc[8][8];
#pragma unroll
    for (int i = 0; i < 8; i++)
#pragma unroll
        for (int j = 0; j < 8; j++) acc[i][j] = 0.0f;

    for (int k0 = 0; k0 < K; k0 += 16) {
#pragma unroll
        for (int h = 0; h < 2; h++) {
            const int row = lrow + h * 64;
            float4 va = *(const float4*)(A + (size_t)(m0 + row) * K + k0 + lcol);
            As[lcol + 0][row] = va.x; As[lcol + 1][row] = va.y;
            As[lcol + 2][row] = va.z; As[lcol + 3][row] = va.w;
            float4 vb = *(const float4*)(B + (size_t)(n0 + row) * K + k0 + lcol);
            Bs[lcol + 0][row] = vb.x; Bs[lcol + 1][row] = vb.y;
            Bs[lcol + 2][row] = vb.z; Bs[lcol + 3][row] = vb.w;
        }
        __syncthreads();

#pragma unroll
        for (int kk = 0; kk < 16; kk++) {
            float a[8], b[8];
            *(float4*)&a[0] = *(const float4*)&As[kk][ty * 8];
            *(float4*)&a[4] = *(const float4*)&As[kk][ty * 8 + 4];
            *(float4*)&b[0] = *(const float4*)&Bs[kk][tx * 8];
            *(float4*)&b[4] = *(const float4*)&Bs[kk][tx * 8 + 4];
#pragma unroll
            for (int i = 0; i < 8; i++)
#pragma unroll
                for (int j = 0; j < 8; j++)
                    acc[i][j] = fmaf(a[i], b[j], acc[i][j]);
        }
        __syncthreads();
    }

    float bb[8];
#pragma unroll
    for (int j = 0; j < 8; j++)
        bb[j] = bias ? bias[n0 + tx * 8 + j] : 0.0f;

#pragma unroll
    for (int i = 0; i < 8; i++) {
        const int m = m0 + ty * 8 + i;
        float4 o0 = make_float4(acc[i][0] + bb[0], acc[i][1] + bb[1],
                                acc[i][2] + bb[2], acc[i][3] + bb[3]);
        float4 o1 = make_float4(acc[i][4] + bb[4], acc[i][5] + bb[5],
                                acc[i][6] + bb[6], acc[i][7] + bb[7]);
        *(float4*)(C + (size_t)m * N + n0 + tx * 8)     = o0;
        *(float4*)(C + (size_t)m * N + n0 + tx * 8 + 4) = o1;
    }
}

// ---------------------------------------------------------------------------
// Flash attention (fp32, online softmax).  One block = one head x 64 queries.
// KV tiles of 64 keys.  256 threads: thread (ty,tx) owns 4 query rows
// (ty*4+i) and, for S, 4 key cols (tx*4+j); for O, 8 d-cols (tx*8+jj).
// Row reductions via shfl across the 16 tx lanes (xor<=8 stays in-half).
// ---------------------------------------------------------------------------
#define QS_STRIDE 132   // pad to dodge bank conflicts on column-wise reads
#define ATT_SMEM_FLOATS (64 * QS_STRIDE * 2 + 64 * 128 + 64 * 64)
#define ATT_SMEM_BYTES  (ATT_SMEM_FLOATS * 4)

__global__ __launch_bounds__(256)
void flash_attn(const float* __restrict__ Qg, const float* __restrict__ Kg,
                const float* __restrict__ Vg, const float* __restrict__ mask,
                float* __restrict__ Og)
{
    extern __shared__ float sm[];
    float* Qs = sm;                        // [64][132]
    float* Ks = Qs + 64 * QS_STRIDE;       // [64][132]
    float* Vs = Ks + 64 * QS_STRIDE;       // [64][128]
    float* Ps = Vs + 64 * 128;             // [64][64]

    const int tid = threadIdx.x;
    const int tx = tid & 15;
    const int ty = tid >> 4;
    const int h = blockIdx.y;
    const int q0 = blockIdx.x * 64;
    const int hoff = h * DHEAD;
    const float scale = 0.08838834764831845f;  // 1/sqrt(128)

    // Load Q tile (64 x 128)
#pragma unroll
    for (int t = 0; t < 8; t++) {
        const int idx = tid + t * 256;
        const int row = idx >> 5;
        const int c4 = (idx & 31) << 2;
        *(float4*)&Qs[row * QS_STRIDE + c4] =
            *(const float4*)&Qg[(size_t)(q0 + row) * HID + hoff + c4];
    }

    float m_i[4], l_i[4], o[4][8];
#pragma unroll
    for (int i = 0; i < 4; i++) {
        m_i[i] = -INFINITY;
        l_i[i] = 0.0f;
#pragma unroll
        for (int jj = 0; jj < 8; jj++) o[i][jj] = 0.0f;
    }

    for (int j0 = 0; j0 < SEQ; j0 += 64) {
        __syncthreads();   // previous iteration's smem reads complete
        // Load K,V tiles
#pragma unroll
        for (int t = 0; t < 8; t++) {
            const int idx = tid + t * 256;
            const int row = idx >> 5;
            const int c4 = (idx & 31) << 2;
            *(float4*)&Ks[row * QS_STRIDE + c4] =
                *(const float4*)&Kg[(size_t)(j0 + row) * HID + hoff + c4];
            *(float4*)&Vs[row * 128 + c4] =
                *(const float4*)&Vg[(size_t)(j0 + row) * HID + hoff + c4];
        }
        __syncthreads();

        // S = Q K^T  (4x4 fragment per thread)
        float s[4][4];
#pragma unroll
        for (int i = 0; i < 4; i++)
#pragma unroll
            for (int j = 0; j < 4; j++) s[i][j] = 0.0f;

#pragma unroll 4
        for (int d0 = 0; d0 < 128; d0 += 4) {
            float4 a[4], b[4];
#pragma unroll
            for (int i = 0; i < 4; i++)
                a[i] = *(const float4*)&Qs[(ty * 4 + i) * QS_STRIDE + d0];
#pragma unroll
            for (int j = 0; j < 4; j++)
                b[j] = *(const float4*)&Ks[(tx * 4 + j) * QS_STRIDE + d0];
#pragma unroll
            for (int i = 0; i < 4; i++)
#pragma unroll
                for (int j = 0; j < 4; j++) {
                    s[i][j] = fmaf(a[i].x, b[j].x, s[i][j]);
                    s[i][j] = fmaf(a[i].y, b[j].y, s[i][j]);
                    s[i][j] = fmaf(a[i].z, b[j].z, s[i][j]);
                    s[i][j] = fmaf(a[i].w, b[j].w, s[i][j]);
                }
        }

        // scale + additive mask
#pragma unroll
        for (int i = 0; i < 4; i++) {
            float4 mk = *(const float4*)&mask[(size_t)(q0 + ty * 4 + i) * SEQ + j0 + tx * 4];
            s[i][0] = s[i][0] * scale + mk.x;
            s[i][1] = s[i][1] * scale + mk.y;
            s[i][2] = s[i][2] * scale + mk.z;
            s[i][3] = s[i][3] * scale + mk.w;
        }

        // Online softmax, write P to shared
#pragma unroll
        for (int i = 0; i < 4; i++) {
            float mx = fmaxf(fmaxf(s[i][0], s[i][1]), fmaxf(s[i][2], s[i][3]));
#pragma unroll
            for (int w = 1; w <= 8; w <<= 1)
                mx = fmaxf(mx, __shfl_xor_sync(0xffffffffu, mx, w));
            const float m_new = fmaxf(m_i[i], mx);
            const float alpha = __expf(m_i[i] - m_new);
            float p0 = __expf(s[i][0] - m_new);
            float p1 = __expf(s[i][1] - m_new);
            float p2 = __expf(s[i][2] - m_new);
            float p3 = __expf(s[i][3] - m_new);
            float rs = p0 + p1 + p2 + p3;
#pragma unroll
            for (int w = 1; w <= 8; w <<= 1)
                rs += __shfl_xor_sync(0xffffffffu, rs, w);
            l_i[i] = l_i[i] * alpha + rs;
            m_i[i] = m_new;
#pragma unroll
            for (int jj = 0; jj < 8; jj++) o[i][jj] *= alpha;
            *(float4*)&Ps[(ty * 4 + i) * 64 + tx * 4] = make_float4(p0, p1, p2, p3);
        }
        __syncthreads();   // Ps visible

        // O += P @ V
#pragma unroll 4
        for (int k = 0; k < 64; k++) {
            float4 v0 = *(const float4*)&Vs[k * 128 + tx * 8];
            float4 v1 = *(const float4*)&Vs[k * 128 + tx * 8 + 4];
#pragma unroll
            for (int i = 0; i < 4; i++) {
                const float p = Ps[(ty * 4 + i) * 64 + k];
                o[i][0] = fmaf(p, v0.x, o[i][0]);
                o[i][1] = fmaf(p, v0.y, o[i][1]);
                o[i][2] = fmaf(p, v0.z, o[i][2]);
                o[i][3] = fmaf(p, v0.w, o[i][3]);
                o[i][4] = fmaf(p, v1.x, o[i][4]);
                o[i][5] = fmaf(p, v1.y, o[i][5]);
                o[i][6] = fmaf(p, v1.z, o[i][6]);
                o[i][7] = fmaf(p, v1.w, o[i][7]);
            }
        }
    }

    // Normalize and write (merge heads: out[q, h*128 + d])
#pragma unroll
    for (int i = 0; i < 4; i++) {
        const float inv = 1.0f / l_i[i];
        float4 w0 = make_float4(o[i][0] * inv, o[i][1] * inv, o[i][2] * inv, o[i][3] * inv);
        float4 w1 = make_float4(o[i][4] * inv, o[i][5] * inv, o[i][6] * inv, o[i][7] * inv);
        float* dst = Og + (size_t)(q0 + ty * 4 + i) * HID + hoff + tx * 8;
        *(float4*)dst = w0;
        *(float4*)(dst + 4) = w1;
    }
}

// ---------------------------------------------------------------------------
// Launch: 3x (x @ V^T) -> 3x (t @ U^T) -> flash attention -> (o @ W^T + b)
// ---------------------------------------------------------------------------
extern "C" void kernel_launch(void* const* d_in, const int* in_sizes, int n_in,
                              void* d_out, int out_size)
{
    (void)in_sizes; (void)n_in; (void)out_size;
    const float* x    = (const float*)d_in[0];
    const float* mask = (const float*)d_in[1];
    const float* Vw[3] = { (const float*)d_in[2], (const float*)d_in[4], (const float*)d_in[6] };
    const float* Uw[3] = { (const float*)d_in[3], (const float*)d_in[5], (const float*)d_in[7] };
    const float* oW = (const float*)d_in[8];
    const float* ob = (const float*)d_in[9];
    float* out = (float*)d_out;

    void *pT, *pQKV, *pAO;
    cudaGetSymbolAddress(&pT, g_T);
    cudaGetSymbolAddress(&pQKV, g_QKV);
    cudaGetSymbolAddress(&pAO, g_AO);
    float* T   = (float*)pT;
    float* QKV = (float*)pQKV;
    float* AO  = (float*)pAO;

    cudaFuncSetAttribute(flash_attn, cudaFuncAttributeMaxDynamicSharedMemorySize,
                         ATT_SMEM_BYTES);

    // Stage 1: T_i = X @ V_i^T      [4096,2048] x [1024,2048]^T -> [4096,1024]
    {
        dim3 grid(RNK / 128, SEQ / 128);
        for (int i = 0; i < 3; i++)
            sgemm_nt<<<grid, 256>>>(x, Vw[i], T + (size_t)i * SEQ * RNK, nullptr,
                                    SEQ, RNK, HID);
    }
    // Stage 2: QKV_i = T_i @ U_i^T  [4096,1024] x [2048,1024]^T -> [4096,2048]
    {
        dim3 grid(HID / 128, SEQ / 128);
        for (int i = 0; i < 3; i++)
            sgemm_nt<<<grid, 256>>>(T + (size_t)i * SEQ * RNK, Uw[i],
                                    QKV + (size_t)i * SEQ * HID, nullptr,
                                    SEQ, HID, RNK);
    }
    // Stage 3: attention per head
    {
        dim3 grid(SEQ / 64, NHEAD);
        flash_attn<<<grid, 256, ATT_SMEM_BYTES>>>(
            QKV, QKV + (size_t)SEQ * HID, QKV + (size_t)2 * SEQ * HID, mask, AO);
    }
    // Stage 4: out = AO @ oW^T + ob
    {
        dim3 grid(HID / 128, SEQ / 128);
        sgemm_nt<<<grid, 256>>>(AO, oW, out, ob, SEQ, HID, HID);
    }
}